// round 2
// baseline (speedup 1.0000x reference)
#include <cuda_runtime.h>
#include <cstdint>

// Quaternion normalization: x viewed as (B, 256, 4); each 4-vector divided by
// its L2 norm (norm==0 -> divide by 1, i.e. pass through zeros).
// Total elements: 65536 * 1024 = 67,108,864 floats = 16,777,216 quaternions.

__device__ __forceinline__ float4 ldg_cs_f4(const float4* p) {
    float4 v;
    asm volatile("ld.global.cs.v4.f32 {%0,%1,%2,%3}, [%4];"
                 : "=f"(v.x), "=f"(v.y), "=f"(v.z), "=f"(v.w)
                 : "l"(p));
    return v;
}

__device__ __forceinline__ void stg_cs_f4(float4* p, float4 v) {
    asm volatile("st.global.cs.v4.f32 [%0], {%1,%2,%3,%4};"
                 :: "l"(p), "f"(v.x), "f"(v.y), "f"(v.z), "f"(v.w));
}

__device__ __forceinline__ float4 norm_quat(float4 q) {
    float s = q.x * q.x + q.y * q.y + q.z * q.z + q.w * q.w;
    // norm==0 -> divide by 1.0 (pass through). Otherwise multiply by rsqrt.
    float inv = (s == 0.0f) ? 1.0f : rsqrtf(s);
    q.x *= inv; q.y *= inv; q.z *= inv; q.w *= inv;
    return q;
}

__global__ void __launch_bounds__(256) quat_norm_kernel(
    const float4* __restrict__ in, float4* __restrict__ out, int n_quats)
{
    // 2 quaternions (2x float4) per thread, front-batched loads for MLP=2.
    int base = (blockIdx.x * blockDim.x + threadIdx.x) * 2;
    if (base + 1 < n_quats) {
        float4 a = ldg_cs_f4(in + base);
        float4 b = ldg_cs_f4(in + base + 1);
        a = norm_quat(a);
        b = norm_quat(b);
        stg_cs_f4(out + base, a);
        stg_cs_f4(out + base + 1, b);
    } else if (base < n_quats) {
        float4 a = ldg_cs_f4(in + base);
        stg_cs_f4(out + base, norm_quat(a));
    }
}

extern "C" void kernel_launch(void* const* d_in, const int* in_sizes, int n_in,
                              void* d_out, int out_size) {
    const float4* in = (const float4*)d_in[0];
    float4* out = (float4*)d_out;
    int n_quats = in_sizes[0] / 4;            // 16,777,216
    int threads = 256;
    int quats_per_block = threads * 2;
    int blocks = (n_quats + quats_per_block - 1) / quats_per_block;  // 32768
    quat_norm_kernel<<<blocks, threads>>>(in, out, n_quats);
}